// round 13
// baseline (speedup 1.0000x reference)
#include <cuda_runtime.h>
#include <math.h>

#define NN   30000
#define FIN  500
#define HID  16
#define NE   960000

typedef unsigned long long ull;

// ---- scratch (static device allocations; no cudaMalloc allowed) ----
__device__ float g_h [NN * HID];   // pooled conv features
__device__ float g_p1[NN * HID];   // (h @ W1) * dinv
__device__ float g_q1[NN * HID];   // aggregated layer-1
__device__ float g_p2[NN * 4];     // (a @ W2) * dinv  (padded to 4, w=0)
__device__ float g_q2[NN * 4];     // aggregated layer-2
__device__ float g_deg [NN];
__device__ float g_dinv[NN];

// ---- packed f32x2 helpers (sm_103a) ----
__device__ __forceinline__ ull ffma2(ull a, ull b, ull c) {
    ull d;
    asm("fma.rn.f32x2 %0, %1, %2, %3;" : "=l"(d) : "l"(a), "l"(b), "l"(c));
    return d;
}
__device__ __forceinline__ ull pack2(float x, float y) {
    ull d;
    asm("mov.b64 %0, {%1, %2};" : "=l"(d) : "f"(x), "f"(y));
    return d;
}
__device__ __forceinline__ void unpack2(ull v, float& x, float& y) {
    asm("mov.b64 {%0, %1}, %2;" : "=f"(x), "=f"(y) : "l"(v));
}
__device__ __forceinline__ void red_add_v4(float* p, float a, float b, float c, float d) {
    asm volatile("red.global.add.v4.f32 [%0], {%1, %2, %3, %4};"
                 :: "l"(p), "f"(a), "f"(b), "f"(c), "f"(d) : "memory");
}

// ============================================================================
// Fused conv1(1->16,k3)+relu + conv2(16->16,k3)+relu + max-pool(len 500)
// One warp per node, 8 warps/block, 2 CTAs/SM (128-reg budget -> no spills).
// Each conv1 channel value is consumed immediately into f32x2-paired conv2
// accumulators. Bias b2 and final relu hoisted past the max-pool.
// ============================================================================
__global__ void __launch_bounds__(256, 2) conv_fused_kernel(
    const float* __restrict__ x,
    const float* __restrict__ w1,   // (16,1,3)
    const float* __restrict__ b1,
    const float* __restrict__ w2,   // (16,16,3)
    const float* __restrict__ b2)
{
    __shared__ float xs[8][506];                       // xs[w][i+2] = x[i]
    __shared__ float w1s[3][16];                       // [k][c]
    __shared__ float b1s[16];
    __shared__ __align__(16) ull w2p[3][16][8];        // [k][ci][co-pair]
    __shared__ float b2s[16];

    const int tid = threadIdx.x;

    // stage conv2 weights as co-pairs: w2p[j][ci][p] = {w2[2p][ci][j], w2[2p+1][ci][j]}
    for (int i = tid; i < 384; i += 256) {
        int j = i / 128, r = i % 128, ci = r / 8, p = r % 8;
        float lo = w2[(2 * p)     * 48 + ci * 3 + j];
        float hi = w2[(2 * p + 1) * 48 + ci * 3 + j];
        w2p[j][ci][p] = pack2(lo, hi);
    }
    if (tid < 48)      w1s[tid % 3][tid / 3] = w1[tid];
    else if (tid < 64) b1s[tid - 48] = b1[tid - 48];
    else if (tid < 80) b2s[tid - 64] = b2[tid - 64];

    const int warp = tid >> 5, lane = tid & 31;
    const int node = blockIdx.x * 8 + warp;            // 3750*8 == 30000

    // stage x row, zero-padded 2 left / 4 right
    const float* xr = x + (size_t)node * FIN;
    for (int i = lane; i < FIN; i += 32) xs[warp][i + 2] = xr[i];
    if (lane < 2)  xs[warp][lane] = 0.f;
    if (lane < 4)  xs[warp][502 + lane] = 0.f;
    __syncthreads();

    float maxv[16];
#pragma unroll
    for (int c = 0; c < 16; c++) maxv[c] = -1e30f;

    for (int it = 0; it < 16; it++) {
        const int traw = it * 32 + lane;
        const bool valid = (traw < FIN);
        const int t = valid ? traw : (FIN - 1);

        // the 5 distinct x values feeding positions t-1, t, t+1
        float xv[5];
#pragma unroll
        for (int q = 0; q < 5; q++) xv[q] = xs[warp][t + q];   // x[t-2+q]

        ull acc[8];
#pragma unroll
        for (int p = 0; p < 8; p++) acc[p] = 0ull;

#pragma unroll
        for (int j = 0; j < 3; j++) {
            const int u = t - 1 + j;                   // in [-1, 500]
            const bool uok = (u >= 0) && (u < FIN);
            const float xm = xv[j], xc = xv[j + 1], xp = xv[j + 2];

#pragma unroll
            for (int ci = 0; ci < 16; ci++) {
                float a = fmaf(w1s[0][ci], xm, b1s[ci]);
                a = fmaf(w1s[1][ci], xc, a);
                a = fmaf(w1s[2][ci], xp, a);
                a = uok ? fmaxf(a, 0.f) : 0.f;
                const ull hh = pack2(a, a);
                const ulonglong2* wr = (const ulonglong2*)w2p[j][ci];
#pragma unroll
                for (int q = 0; q < 4; q++) {
                    ulonglong2 wv = wr[q];
                    acc[2 * q]     = ffma2(wv.x, hh, acc[2 * q]);
                    acc[2 * q + 1] = ffma2(wv.y, hh, acc[2 * q + 1]);
                }
            }
        }

        if (valid) {
#pragma unroll
            for (int p = 0; p < 8; p++) {
                float a0, a1; unpack2(acc[p], a0, a1);
                maxv[2 * p]     = fmaxf(maxv[2 * p],     a0);
                maxv[2 * p + 1] = fmaxf(maxv[2 * p + 1], a1);
            }
        }
    }

    // warp max-reduce; then +b2 and relu (both commute past the max)
#pragma unroll
    for (int c = 0; c < 16; c++) {
        float v = maxv[c];
#pragma unroll
        for (int off = 16; off > 0; off >>= 1)
            v = fmaxf(v, __shfl_xor_sync(0xffffffffu, v, off));
        maxv[c] = v;
    }
    if (lane == 0) {
#pragma unroll
        for (int c = 0; c < 16; c++)
            g_h[node * 16 + c] = fmaxf(maxv[c] + b2s[c], 0.f);
    }
}

// ============================================================================
// Degree / dinv
// ============================================================================
__global__ void deg_init_kernel()
{
    int i = blockIdx.x * 256 + threadIdx.x;
    if (i < NN) g_deg[i] = 1.0f;            // self loop
}

__global__ void deg_count_kernel(const int* __restrict__ ei)
{
    int e = blockIdx.x * 256 + threadIdx.x;
    if (e < NE) atomicAdd(&g_deg[ei[NE + e]], 1.0f);   // dst
}

__global__ void dinv_kernel()
{
    int i = blockIdx.x * 256 + threadIdx.x;
    if (i < NN) g_dinv[i] = rsqrtf(g_deg[i]);
}

// ============================================================================
// GCN layer 1 pre: p1 = (h @ W1) * dinv ; q1 = p1 (self-loop term)
// ============================================================================
__global__ void __launch_bounds__(256) gcn1_pre_kernel(const float* __restrict__ W)
{
    __shared__ float Ws[256];
    Ws[threadIdx.x] = W[threadIdx.x];
    __syncthreads();

    int node = blockIdx.x * 256 + threadIdx.x;
    if (node >= NN) return;

    const float4* hr = (const float4*)(g_h + node * 16);
    float hv[16];
    float4 t0 = hr[0], t1 = hr[1], t2 = hr[2], t3 = hr[3];
    hv[0]=t0.x; hv[1]=t0.y; hv[2]=t0.z; hv[3]=t0.w;
    hv[4]=t1.x; hv[5]=t1.y; hv[6]=t1.z; hv[7]=t1.w;
    hv[8]=t2.x; hv[9]=t2.y; hv[10]=t2.z; hv[11]=t2.w;
    hv[12]=t3.x; hv[13]=t3.y; hv[14]=t3.z; hv[15]=t3.w;

    float acc[16];
#pragma unroll
    for (int c = 0; c < 16; c++) acc[c] = 0.f;
#pragma unroll
    for (int ci = 0; ci < 16; ci++) {
        const float hvi = hv[ci];
#pragma unroll
        for (int c4 = 0; c4 < 4; c4++) {
            const float4 w = *(const float4*)&Ws[ci * 16 + c4 * 4];
            acc[c4*4+0] = fmaf(hvi, w.x, acc[c4*4+0]);
            acc[c4*4+1] = fmaf(hvi, w.y, acc[c4*4+1]);
            acc[c4*4+2] = fmaf(hvi, w.z, acc[c4*4+2]);
            acc[c4*4+3] = fmaf(hvi, w.w, acc[c4*4+3]);
        }
    }
    const float di = g_dinv[node];
    float4* pp = (float4*)(g_p1 + node * 16);
    float4* qq = (float4*)(g_q1 + node * 16);
#pragma unroll
    for (int c4 = 0; c4 < 4; c4++) {
        float4 v;
        v.x = acc[c4*4+0]*di; v.y = acc[c4*4+1]*di;
        v.z = acc[c4*4+2]*di; v.w = acc[c4*4+3]*di;
        pp[c4] = v; qq[c4] = v;
    }
}

// ============================================================================
// Edge aggregation layer 1: q1[dst] += p1[src]  (4 threads/edge, REDG.128)
// ============================================================================
__global__ void edge_agg16_kernel(const int* __restrict__ ei)
{
    int tid = blockIdx.x * 256 + threadIdx.x;
    int e = tid >> 2;
    if (e >= NE) return;
    int j = tid & 3;
    int s = __ldg(ei + e), d = __ldg(ei + NE + e);
    float4 v = *(const float4*)(g_p1 + s * 16 + j * 4);
    red_add_v4(g_q1 + d * 16 + j * 4, v.x, v.y, v.z, v.w);
}

// ============================================================================
// GCN layer 2 pre: a = relu(dinv*q1 + b1) ; p2 = (a @ W2) * dinv ; q2 = p2
// ============================================================================
__global__ void __launch_bounds__(256) gcn2_pre_kernel(
    const float* __restrict__ b1g, const float* __restrict__ W2)
{
    __shared__ float W2s[48];
    __shared__ float b1s[16];
    if (threadIdx.x < 48) W2s[threadIdx.x] = W2[threadIdx.x];
    if (threadIdx.x < 16) b1s[threadIdx.x] = b1g[threadIdx.x];
    __syncthreads();

    int node = blockIdx.x * 256 + threadIdx.x;
    if (node >= NN) return;

    const float di = g_dinv[node];
    const float4* qr = (const float4*)(g_q1 + node * 16);
    float a[16];
#pragma unroll
    for (int c4 = 0; c4 < 4; c4++) {
        float4 v = qr[c4];
        a[c4*4+0] = fmaxf(fmaf(di, v.x, b1s[c4*4+0]), 0.f);
        a[c4*4+1] = fmaxf(fmaf(di, v.y, b1s[c4*4+1]), 0.f);
        a[c4*4+2] = fmaxf(fmaf(di, v.z, b1s[c4*4+2]), 0.f);
        a[c4*4+3] = fmaxf(fmaf(di, v.w, b1s[c4*4+3]), 0.f);
    }
    float o0 = 0.f, o1 = 0.f, o2 = 0.f;
#pragma unroll
    for (int ci = 0; ci < 16; ci++) {
        o0 = fmaf(a[ci], W2s[ci * 3 + 0], o0);
        o1 = fmaf(a[ci], W2s[ci * 3 + 1], o1);
        o2 = fmaf(a[ci], W2s[ci * 3 + 2], o2);
    }
    float4 r; r.x = o0 * di; r.y = o1 * di; r.z = o2 * di; r.w = 0.f;
    *(float4*)(g_p2 + node * 4) = r;
    *(float4*)(g_q2 + node * 4) = r;
}

// ============================================================================
// Edge aggregation layer 2: q2[dst] += p2[src]  (1 REDG.128/edge; w adds 0)
// ============================================================================
__global__ void edge_agg3_kernel(const int* __restrict__ ei)
{
    int e = blockIdx.x * 256 + threadIdx.x;
    if (e >= NE) return;
    int s = __ldg(ei + e), d = __ldg(ei + NE + e);
    float4 v = *(const float4*)(g_p2 + s * 4);
    red_add_v4(g_q2 + d * 4, v.x, v.y, v.z, v.w);
}

// ============================================================================
// Finalize: v = dinv*q2 + b2 ; log_softmax over 3 classes
// ============================================================================
__global__ void finalize_kernel(const float* __restrict__ b2g, float* __restrict__ out)
{
    int node = blockIdx.x * 256 + threadIdx.x;
    if (node >= NN) return;
    const float di = g_dinv[node];
    float4 q = *(const float4*)(g_q2 + node * 4);
    float v0 = fmaf(di, q.x, b2g[0]);
    float v1 = fmaf(di, q.y, b2g[1]);
    float v2 = fmaf(di, q.z, b2g[2]);
    float m = fmaxf(v0, fmaxf(v1, v2));
    float s = expf(v0 - m) + expf(v1 - m) + expf(v2 - m);
    float l = m + logf(s);
    out[node * 3 + 0] = v0 - l;
    out[node * 3 + 1] = v1 - l;
    out[node * 3 + 2] = v2 - l;
}

// ============================================================================
extern "C" void kernel_launch(void* const* d_in, const int* in_sizes, int n_in,
                              void* d_out, int out_size)
{
    const float* x   = (const float*)d_in[0];
    const float* c1w = (const float*)d_in[1];
    const float* c1b = (const float*)d_in[2];
    const float* c2w = (const float*)d_in[3];
    const float* c2b = (const float*)d_in[4];
    const float* g1w = (const float*)d_in[5];
    const float* g1b = (const float*)d_in[6];
    const float* g2w = (const float*)d_in[7];
    const float* g2b = (const float*)d_in[8];
    const int*   ei  = (const int*)d_in[9];
    float* out = (float*)d_out;

    const int nblk_node = (NN + 255) / 256;   // 118
    const int nblk_edge = (NE + 255) / 256;   // 3750

    deg_init_kernel <<<nblk_node, 256>>>();
    deg_count_kernel<<<nblk_edge, 256>>>(ei);
    dinv_kernel     <<<nblk_node, 256>>>();

    conv_fused_kernel<<<NN / 8, 256>>>(x, c1w, c1b, c2w, c2b);

    gcn1_pre_kernel <<<nblk_node, 256>>>(g1w);
    edge_agg16_kernel<<<(4 * NE + 255) / 256, 256>>>(ei);

    gcn2_pre_kernel <<<nblk_node, 256>>>(g1b, g2w);
    edge_agg3_kernel<<<nblk_edge, 256>>>(ei);

    finalize_kernel <<<nblk_node, 256>>>(g2b, out);
}

// round 15
// speedup vs baseline: 5.1250x; 5.1250x over previous
#include <cuda_runtime.h>
#include <math.h>

#define NN   30000
#define FIN  500
#define HID  16
#define NE   960000

typedef unsigned long long ull;

// ---- scratch (static device allocations; no cudaMalloc allowed) ----
__device__ float g_h [NN * HID];   // pooled conv features
__device__ float g_p1[NN * HID];   // (h @ W1) * dinv
__device__ float g_q1[NN * HID];   // aggregated layer-1
__device__ float g_p2[NN * 4];     // (a @ W2) * dinv  (padded to 4, w=0)
__device__ float g_q2[NN * 4];     // aggregated layer-2
__device__ float g_deg [NN];
__device__ float g_dinv[NN];

// ---- packed f32x2 helpers (sm_103a) ----
__device__ __forceinline__ ull ffma2(ull a, ull b, ull c) {
    ull d;
    asm("fma.rn.f32x2 %0, %1, %2, %3;" : "=l"(d) : "l"(a), "l"(b), "l"(c));
    return d;
}
__device__ __forceinline__ ull pack2(float x, float y) {
    ull d;
    asm("mov.b64 %0, {%1, %2};" : "=l"(d) : "f"(x), "f"(y));
    return d;
}
__device__ __forceinline__ void unpack2(ull v, float& x, float& y) {
    asm("mov.b64 {%0, %1}, %2;" : "=f"(x), "=f"(y) : "l"(v));
}
__device__ __forceinline__ void red_add_v4(float* p, float a, float b, float c, float d) {
    asm volatile("red.global.add.v4.f32 [%0], {%1, %2, %3, %4};"
                 :: "l"(p), "f"(a), "f"(b), "f"(c), "f"(d) : "memory");
}

// ============================================================================
// Fused conv1(1->16,k3)+relu + conv2(16->16,k3)+relu + max-pool(len 500)
// One warp per node, 8 warps/block, 2 CTAs/SM. The ci loop is unrolled only
// 2x so ptxas's LDS-batching window stays small and the accumulators remain
// register-resident (no local-memory spills).
// ============================================================================
__global__ void __launch_bounds__(256, 2) conv_fused_kernel(
    const float* __restrict__ x,
    const float* __restrict__ w1,   // (16,1,3)
    const float* __restrict__ b1,
    const float* __restrict__ w2,   // (16,16,3)
    const float* __restrict__ b2)
{
    __shared__ float xs[8][506];                       // xs[w][i+2] = x[i]
    __shared__ float w1s[3][16];                       // [k][c]
    __shared__ float b1s[16];
    __shared__ __align__(16) ull w2p[3][16][8];        // [k][ci][co-pair]
    __shared__ float b2s[16];

    const int tid = threadIdx.x;

    // stage conv2 weights as co-pairs: w2p[j][ci][p] = {w2[2p][ci][j], w2[2p+1][ci][j]}
    for (int i = tid; i < 384; i += 256) {
        int j = i / 128, r = i % 128, ci = r / 8, p = r % 8;
        float lo = w2[(2 * p)     * 48 + ci * 3 + j];
        float hi = w2[(2 * p + 1) * 48 + ci * 3 + j];
        w2p[j][ci][p] = pack2(lo, hi);
    }
    if (tid < 48)      w1s[tid % 3][tid / 3] = w1[tid];
    else if (tid < 64) b1s[tid - 48] = b1[tid - 48];
    else if (tid < 80) b2s[tid - 64] = b2[tid - 64];

    const int warp = tid >> 5, lane = tid & 31;
    const int node = blockIdx.x * 8 + warp;            // 3750*8 == 30000

    // stage x row, zero-padded 2 left / 4 right
    const float* xr = x + (size_t)node * FIN;
    for (int i = lane; i < FIN; i += 32) xs[warp][i + 2] = xr[i];
    if (lane < 2)  xs[warp][lane] = 0.f;
    if (lane < 4)  xs[warp][502 + lane] = 0.f;
    __syncthreads();

    float maxv[16];
#pragma unroll
    for (int c = 0; c < 16; c++) maxv[c] = -1e30f;

    for (int it = 0; it < 16; it++) {
        const int traw = it * 32 + lane;
        const bool valid = (traw < FIN);
        const int t = valid ? traw : (FIN - 1);

        // the 5 distinct x values feeding positions t-1, t, t+1
        float xv[5];
#pragma unroll
        for (int q = 0; q < 5; q++) xv[q] = xs[warp][t + q];   // x[t-2+q]

        ull acc[8];
#pragma unroll
        for (int p = 0; p < 8; p++) acc[p] = 0ull;

#pragma unroll
        for (int j = 0; j < 3; j++) {
            const int u = t - 1 + j;                   // in [-1, 500]
            const bool uok = (u >= 0) && (u < FIN);
            const float xm = xv[j], xc = xv[j + 1], xp = xv[j + 2];

#pragma unroll 2
            for (int ci = 0; ci < 16; ci++) {
                float a = fmaf(w1s[0][ci], xm, b1s[ci]);
                a = fmaf(w1s[1][ci], xc, a);
                a = fmaf(w1s[2][ci], xp, a);
                a = uok ? fmaxf(a, 0.f) : 0.f;
                const ull hh = pack2(a, a);
                const ulonglong2* wr = (const ulonglong2*)w2p[j][ci];
#pragma unroll
                for (int q = 0; q < 4; q++) {
                    ulonglong2 wv = wr[q];
                    acc[2 * q]     = ffma2(wv.x, hh, acc[2 * q]);
                    acc[2 * q + 1] = ffma2(wv.y, hh, acc[2 * q + 1]);
                }
            }
        }

        if (valid) {
#pragma unroll
            for (int p = 0; p < 8; p++) {
                float a0, a1; unpack2(acc[p], a0, a1);
                maxv[2 * p]     = fmaxf(maxv[2 * p],     a0);
                maxv[2 * p + 1] = fmaxf(maxv[2 * p + 1], a1);
            }
        }
    }

    // warp max-reduce; then +b2 and relu (both commute past the max)
#pragma unroll
    for (int c = 0; c < 16; c++) {
        float v = maxv[c];
#pragma unroll
        for (int off = 16; off > 0; off >>= 1)
            v = fmaxf(v, __shfl_xor_sync(0xffffffffu, v, off));
        maxv[c] = v;
    }
    if (lane == 0) {
#pragma unroll
        for (int c = 0; c < 16; c++)
            g_h[node * 16 + c] = fmaxf(maxv[c] + b2s[c], 0.f);
    }
}

// ============================================================================
// Degree / dinv
// ============================================================================
__global__ void deg_init_kernel()
{
    int i = blockIdx.x * 256 + threadIdx.x;
    if (i < NN) g_deg[i] = 1.0f;            // self loop
}

__global__ void deg_count_kernel(const int* __restrict__ ei)
{
    int e = blockIdx.x * 256 + threadIdx.x;
    if (e < NE) atomicAdd(&g_deg[ei[NE + e]], 1.0f);   // dst
}

__global__ void dinv_kernel()
{
    int i = blockIdx.x * 256 + threadIdx.x;
    if (i < NN) g_dinv[i] = rsqrtf(g_deg[i]);
}

// ============================================================================
// GCN layer 1 pre: p1 = (h @ W1) * dinv ; q1 = p1 (self-loop term)
// ============================================================================
__global__ void __launch_bounds__(256) gcn1_pre_kernel(const float* __restrict__ W)
{
    __shared__ float Ws[256];
    Ws[threadIdx.x] = W[threadIdx.x];
    __syncthreads();

    int node = blockIdx.x * 256 + threadIdx.x;
    if (node >= NN) return;

    const float4* hr = (const float4*)(g_h + node * 16);
    float hv[16];
    float4 t0 = hr[0], t1 = hr[1], t2 = hr[2], t3 = hr[3];
    hv[0]=t0.x; hv[1]=t0.y; hv[2]=t0.z; hv[3]=t0.w;
    hv[4]=t1.x; hv[5]=t1.y; hv[6]=t1.z; hv[7]=t1.w;
    hv[8]=t2.x; hv[9]=t2.y; hv[10]=t2.z; hv[11]=t2.w;
    hv[12]=t3.x; hv[13]=t3.y; hv[14]=t3.z; hv[15]=t3.w;

    float acc[16];
#pragma unroll
    for (int c = 0; c < 16; c++) acc[c] = 0.f;
#pragma unroll
    for (int ci = 0; ci < 16; ci++) {
        const float hvi = hv[ci];
#pragma unroll
        for (int c4 = 0; c4 < 4; c4++) {
            const float4 w = *(const float4*)&Ws[ci * 16 + c4 * 4];
            acc[c4*4+0] = fmaf(hvi, w.x, acc[c4*4+0]);
            acc[c4*4+1] = fmaf(hvi, w.y, acc[c4*4+1]);
            acc[c4*4+2] = fmaf(hvi, w.z, acc[c4*4+2]);
            acc[c4*4+3] = fmaf(hvi, w.w, acc[c4*4+3]);
        }
    }
    const float di = g_dinv[node];
    float4* pp = (float4*)(g_p1 + node * 16);
    float4* qq = (float4*)(g_q1 + node * 16);
#pragma unroll
    for (int c4 = 0; c4 < 4; c4++) {
        float4 v;
        v.x = acc[c4*4+0]*di; v.y = acc[c4*4+1]*di;
        v.z = acc[c4*4+2]*di; v.w = acc[c4*4+3]*di;
        pp[c4] = v; qq[c4] = v;
    }
}

// ============================================================================
// Edge aggregation layer 1: q1[dst] += p1[src]  (4 threads/edge, REDG.128)
// ============================================================================
__global__ void edge_agg16_kernel(const int* __restrict__ ei)
{
    int tid = blockIdx.x * 256 + threadIdx.x;
    int e = tid >> 2;
    if (e >= NE) return;
    int j = tid & 3;
    int s = __ldg(ei + e), d = __ldg(ei + NE + e);
    float4 v = *(const float4*)(g_p1 + s * 16 + j * 4);
    red_add_v4(g_q1 + d * 16 + j * 4, v.x, v.y, v.z, v.w);
}

// ============================================================================
// GCN layer 2 pre: a = relu(dinv*q1 + b1) ; p2 = (a @ W2) * dinv ; q2 = p2
// ============================================================================
__global__ void __launch_bounds__(256) gcn2_pre_kernel(
    const float* __restrict__ b1g, const float* __restrict__ W2)
{
    __shared__ float W2s[48];
    __shared__ float b1s[16];
    if (threadIdx.x < 48) W2s[threadIdx.x] = W2[threadIdx.x];
    if (threadIdx.x < 16) b1s[threadIdx.x] = b1g[threadIdx.x];
    __syncthreads();

    int node = blockIdx.x * 256 + threadIdx.x;
    if (node >= NN) return;

    const float di = g_dinv[node];
    const float4* qr = (const float4*)(g_q1 + node * 16);
    float a[16];
#pragma unroll
    for (int c4 = 0; c4 < 4; c4++) {
        float4 v = qr[c4];
        a[c4*4+0] = fmaxf(fmaf(di, v.x, b1s[c4*4+0]), 0.f);
        a[c4*4+1] = fmaxf(fmaf(di, v.y, b1s[c4*4+1]), 0.f);
        a[c4*4+2] = fmaxf(fmaf(di, v.z, b1s[c4*4+2]), 0.f);
        a[c4*4+3] = fmaxf(fmaf(di, v.w, b1s[c4*4+3]), 0.f);
    }
    float o0 = 0.f, o1 = 0.f, o2 = 0.f;
#pragma unroll
    for (int ci = 0; ci < 16; ci++) {
        o0 = fmaf(a[ci], W2s[ci * 3 + 0], o0);
        o1 = fmaf(a[ci], W2s[ci * 3 + 1], o1);
        o2 = fmaf(a[ci], W2s[ci * 3 + 2], o2);
    }
    float4 r; r.x = o0 * di; r.y = o1 * di; r.z = o2 * di; r.w = 0.f;
    *(float4*)(g_p2 + node * 4) = r;
    *(float4*)(g_q2 + node * 4) = r;
}

// ============================================================================
// Edge aggregation layer 2: q2[dst] += p2[src]  (1 REDG.128/edge; w adds 0)
// ============================================================================
__global__ void edge_agg3_kernel(const int* __restrict__ ei)
{
    int e = blockIdx.x * 256 + threadIdx.x;
    if (e >= NE) return;
    int s = __ldg(ei + e), d = __ldg(ei + NE + e);
    float4 v = *(const float4*)(g_p2 + s * 4);
    red_add_v4(g_q2 + d * 4, v.x, v.y, v.z, v.w);
}

// ============================================================================
// Finalize: v = dinv*q2 + b2 ; log_softmax over 3 classes
// ============================================================================
__global__ void finalize_kernel(const float* __restrict__ b2g, float* __restrict__ out)
{
    int node = blockIdx.x * 256 + threadIdx.x;
    if (node >= NN) return;
    const float di = g_dinv[node];
    float4 q = *(const float4*)(g_q2 + node * 4);
    float v0 = fmaf(di, q.x, b2g[0]);
    float v1 = fmaf(di, q.y, b2g[1]);
    float v2 = fmaf(di, q.z, b2g[2]);
    float m = fmaxf(v0, fmaxf(v1, v2));
    float s = expf(v0 - m) + expf(v1 - m) + expf(v2 - m);
    float l = m + logf(s);
    out[node * 3 + 0] = v0 - l;
    out[node * 3 + 1] = v1 - l;
    out[node * 3 + 2] = v2 - l;
}

// ============================================================================
extern "C" void kernel_launch(void* const* d_in, const int* in_sizes, int n_in,
                              void* d_out, int out_size)
{
    const float* x   = (const float*)d_in[0];
    const float* c1w = (const float*)d_in[1];
    const float* c1b = (const float*)d_in[2];
    const float* c2w = (const float*)d_in[3];
    const float* c2b = (const float*)d_in[4];
    const float* g1w = (const float*)d_in[5];
    const float* g1b = (const float*)d_in[6];
    const float* g2w = (const float*)d_in[7];
    const float* g2b = (const float*)d_in[8];
    const int*   ei  = (const int*)d_in[9];
    float* out = (float*)d_out;

    const int nblk_node = (NN + 255) / 256;   // 118
    const int nblk_edge = (NE + 255) / 256;   // 3750

    deg_init_kernel <<<nblk_node, 256>>>();
    deg_count_kernel<<<nblk_edge, 256>>>(ei);
    dinv_kernel     <<<nblk_node, 256>>>();

    conv_fused_kernel<<<NN / 8, 256>>>(x, c1w, c1b, c2w, c2b);

    gcn1_pre_kernel <<<nblk_node, 256>>>(g1w);
    edge_agg16_kernel<<<(4 * NE + 255) / 256, 256>>>(ei);

    gcn2_pre_kernel <<<nblk_node, 256>>>(g1b, g2w);
    edge_agg3_kernel<<<nblk_edge, 256>>>(ei);

    finalize_kernel <<<nblk_node, 256>>>(g2b, out);
}

// round 16
// speedup vs baseline: 10.0540x; 1.9618x over previous
#include <cuda_runtime.h>
#include <math.h>

#define NN   30000
#define FIN  500
#define HID  16
#define NE   960000

typedef unsigned long long ull;

// ---- scratch (static device allocations; no cudaMalloc allowed) ----
__device__ float g_h [NN * HID];   // pooled conv features
__device__ float g_p1[NN * HID];   // (h @ W1) * dinv
__device__ float g_q1[NN * HID];   // aggregated layer-1
__device__ float g_p2[NN * 4];     // (a @ W2) * dinv  (padded to 4, w=0)
__device__ float g_q2[NN * 4];     // aggregated layer-2
__device__ float g_deg [NN];
__device__ float g_dinv[NN];

// ---- packed f32x2 helpers (sm_103a) ----
__device__ __forceinline__ ull ffma2(ull a, ull b, ull c) {
    ull d;
    asm("fma.rn.f32x2 %0, %1, %2, %3;" : "=l"(d) : "l"(a), "l"(b), "l"(c));
    return d;
}
__device__ __forceinline__ ull pack2(float x, float y) {
    ull d;
    asm("mov.b64 %0, {%1, %2};" : "=l"(d) : "f"(x), "f"(y));
    return d;
}
__device__ __forceinline__ void unpack2(ull v, float& x, float& y) {
    asm("mov.b64 {%0, %1}, %2;" : "=f"(x), "=f"(y) : "l"(v));
}
__device__ __forceinline__ void red_add_v4(float* p, float a, float b, float c, float d) {
    asm volatile("red.global.add.v4.f32 [%0], {%1, %2, %3, %4};"
                 :: "l"(p), "f"(a), "f"(b), "f"(c), "f"(d) : "memory");
}

// ============================================================================
// Fused conv1(1->16,k3)+relu + conv2(16->16,k3)+relu + max-pool(len 500)
// One warp per node, 8 warps/block, 2 CTAs/SM.
// ci-outer / j-inner loop order: per ci one LDS.128 fetches {w1[0..2],b1},
// the 3 conv1 taps are computed together, then 6 LDS.128 fetch the w2 pairs.
// 112 L1 wavefronts/iter (was 293). unroll 2 keeps the LDS window bounded so
// accumulators stay register-resident (no spills; see R15 regs=94).
// ============================================================================
__global__ void __launch_bounds__(256, 2) conv_fused_kernel(
    const float* __restrict__ x,
    const float* __restrict__ w1,   // (16,1,3)
    const float* __restrict__ b1,
    const float* __restrict__ w2,   // (16,16,3)
    const float* __restrict__ b2)
{
    __shared__ float xs[8][506];                       // xs[w][i+2] = x[i]
    __shared__ __align__(16) float4 w1b1s[16];         // {w1k0, w1k1, w1k2, b1}
    __shared__ __align__(16) ull w2p[3][16][8];        // [k][ci][co-pair]
    __shared__ float b2s[16];

    const int tid = threadIdx.x;

    // stage conv2 weights as co-pairs: w2p[j][ci][p] = {w2[2p][ci][j], w2[2p+1][ci][j]}
    for (int i = tid; i < 384; i += 256) {
        int j = i / 128, r = i % 128, ci = r / 8, p = r % 8;
        float lo = w2[(2 * p)     * 48 + ci * 3 + j];
        float hi = w2[(2 * p + 1) * 48 + ci * 3 + j];
        w2p[j][ci][p] = pack2(lo, hi);
    }
    if (tid < 16) {
        float4 wb;
        wb.x = w1[tid * 3 + 0];
        wb.y = w1[tid * 3 + 1];
        wb.z = w1[tid * 3 + 2];
        wb.w = b1[tid];
        w1b1s[tid] = wb;
    } else if (tid < 32) {
        b2s[tid - 16] = b2[tid - 16];
    }

    const int warp = tid >> 5, lane = tid & 31;
    const int node = blockIdx.x * 8 + warp;            // 3750*8 == 30000

    // stage x row, zero-padded 2 left / 4 right
    const float* xr = x + (size_t)node * FIN;
    for (int i = lane; i < FIN; i += 32) xs[warp][i + 2] = xr[i];
    if (lane < 2)  xs[warp][lane] = 0.f;
    if (lane < 4)  xs[warp][502 + lane] = 0.f;
    __syncthreads();

    float maxv[16];
#pragma unroll
    for (int c = 0; c < 16; c++) maxv[c] = -1e30f;

    for (int it = 0; it < 16; it++) {
        const int traw = it * 32 + lane;
        const bool valid = (traw < FIN);
        const int t = valid ? traw : (FIN - 1);

        // validity of the three conv2 taps u = t-1, t, t+1 (t in [0,499])
        const bool uok0 = (t >= 1);
        const bool uok2 = (t < FIN - 1);

        // the 5 distinct x values feeding positions t-1, t, t+1
        float xv[5];
#pragma unroll
        for (int q = 0; q < 5; q++) xv[q] = xs[warp][t + q];   // x[t-2+q]

        ull acc[8];
#pragma unroll
        for (int p = 0; p < 8; p++) acc[p] = 0ull;

#pragma unroll 2
        for (int ci = 0; ci < 16; ci++) {
            const float4 wb = w1b1s[ci];

            // conv1 channel ci at u = t-1, t, t+1
            float h[3];
#pragma unroll
            for (int j = 0; j < 3; j++) {
                float a = fmaf(wb.x, xv[j], wb.w);
                a = fmaf(wb.y, xv[j + 1], a);
                a = fmaf(wb.z, xv[j + 2], a);
                h[j] = fmaxf(a, 0.f);
            }
            if (!uok0) h[0] = 0.f;
            if (!uok2) h[2] = 0.f;

            // conv2: fold the 3 taps of channel ci into the 16 accumulators
#pragma unroll
            for (int j = 0; j < 3; j++) {
                const ull hh = pack2(h[j], h[j]);
                const ulonglong2* wr = (const ulonglong2*)w2p[j][ci];
                ulonglong2 w0 = wr[0], w1v = wr[1];
                acc[0] = ffma2(w0.x,  hh, acc[0]);
                acc[1] = ffma2(w0.y,  hh, acc[1]);
                acc[2] = ffma2(w1v.x, hh, acc[2]);
                acc[3] = ffma2(w1v.y, hh, acc[3]);
                wr = (const ulonglong2*)&w2p[j][ci][4];
                ulonglong2 w2a = wr[0], w2b = wr[1];
                acc[4] = ffma2(w2a.x, hh, acc[4]);
                acc[5] = ffma2(w2a.y, hh, acc[5]);
                acc[6] = ffma2(w2b.x, hh, acc[6]);
                acc[7] = ffma2(w2b.y, hh, acc[7]);
            }
        }

        if (valid) {
#pragma unroll
            for (int p = 0; p < 8; p++) {
                float a0, a1; unpack2(acc[p], a0, a1);
                maxv[2 * p]     = fmaxf(maxv[2 * p],     a0);
                maxv[2 * p + 1] = fmaxf(maxv[2 * p + 1], a1);
            }
        }
    }

    // warp max-reduce; then +b2 and relu (both commute past the max)
#pragma unroll
    for (int c = 0; c < 16; c++) {
        float v = maxv[c];
#pragma unroll
        for (int off = 16; off > 0; off >>= 1)
            v = fmaxf(v, __shfl_xor_sync(0xffffffffu, v, off));
        maxv[c] = v;
    }
    if (lane == 0) {
#pragma unroll
        for (int c = 0; c < 16; c++)
            g_h[node * 16 + c] = fmaxf(maxv[c] + b2s[c], 0.f);
    }
}

// ============================================================================
// Degree / dinv
// ============================================================================
__global__ void deg_init_kernel()
{
    int i = blockIdx.x * 256 + threadIdx.x;
    if (i < NN) g_deg[i] = 1.0f;            // self loop
}

__global__ void deg_count_kernel(const int* __restrict__ ei)
{
    int e = blockIdx.x * 256 + threadIdx.x;
    if (e < NE) atomicAdd(&g_deg[ei[NE + e]], 1.0f);   // dst
}

__global__ void dinv_kernel()
{
    int i = blockIdx.x * 256 + threadIdx.x;
    if (i < NN) g_dinv[i] = rsqrtf(g_deg[i]);
}

// ============================================================================
// GCN layer 1 pre: p1 = (h @ W1) * dinv ; q1 = p1 (self-loop term)
// ============================================================================
__global__ void __launch_bounds__(256) gcn1_pre_kernel(const float* __restrict__ W)
{
    __shared__ float Ws[256];
    Ws[threadIdx.x] = W[threadIdx.x];
    __syncthreads();

    int node = blockIdx.x * 256 + threadIdx.x;
    if (node >= NN) return;

    const float4* hr = (const float4*)(g_h + node * 16);
    float hv[16];
    float4 t0 = hr[0], t1 = hr[1], t2 = hr[2], t3 = hr[3];
    hv[0]=t0.x; hv[1]=t0.y; hv[2]=t0.z; hv[3]=t0.w;
    hv[4]=t1.x; hv[5]=t1.y; hv[6]=t1.z; hv[7]=t1.w;
    hv[8]=t2.x; hv[9]=t2.y; hv[10]=t2.z; hv[11]=t2.w;
    hv[12]=t3.x; hv[13]=t3.y; hv[14]=t3.z; hv[15]=t3.w;

    float acc[16];
#pragma unroll
    for (int c = 0; c < 16; c++) acc[c] = 0.f;
#pragma unroll
    for (int ci = 0; ci < 16; ci++) {
        const float hvi = hv[ci];
#pragma unroll
        for (int c4 = 0; c4 < 4; c4++) {
            const float4 w = *(const float4*)&Ws[ci * 16 + c4 * 4];
            acc[c4*4+0] = fmaf(hvi, w.x, acc[c4*4+0]);
            acc[c4*4+1] = fmaf(hvi, w.y, acc[c4*4+1]);
            acc[c4*4+2] = fmaf(hvi, w.z, acc[c4*4+2]);
            acc[c4*4+3] = fmaf(hvi, w.w, acc[c4*4+3]);
        }
    }
    const float di = g_dinv[node];
    float4* pp = (float4*)(g_p1 + node * 16);
    float4* qq = (float4*)(g_q1 + node * 16);
#pragma unroll
    for (int c4 = 0; c4 < 4; c4++) {
        float4 v;
        v.x = acc[c4*4+0]*di; v.y = acc[c4*4+1]*di;
        v.z = acc[c4*4+2]*di; v.w = acc[c4*4+3]*di;
        pp[c4] = v; qq[c4] = v;
    }
}

// ============================================================================
// Edge aggregation layer 1: q1[dst] += p1[src]  (4 threads/edge, REDG.128)
// ============================================================================
__global__ void edge_agg16_kernel(const int* __restrict__ ei)
{
    int tid = blockIdx.x * 256 + threadIdx.x;
    int e = tid >> 2;
    if (e >= NE) return;
    int j = tid & 3;
    int s = __ldg(ei + e), d = __ldg(ei + NE + e);
    float4 v = *(const float4*)(g_p1 + s * 16 + j * 4);
    red_add_v4(g_q1 + d * 16 + j * 4, v.x, v.y, v.z, v.w);
}

// ============================================================================
// GCN layer 2 pre: a = relu(dinv*q1 + b1) ; p2 = (a @ W2) * dinv ; q2 = p2
// ============================================================================
__global__ void __launch_bounds__(256) gcn2_pre_kernel(
    const float* __restrict__ b1g, const float* __restrict__ W2)
{
    __shared__ float W2s[48];
    __shared__ float b1s[16];
    if (threadIdx.x < 48) W2s[threadIdx.x] = W2[threadIdx.x];
    if (threadIdx.x < 16) b1s[threadIdx.x] = b1g[threadIdx.x];
    __syncthreads();

    int node = blockIdx.x * 256 + threadIdx.x;
    if (node >= NN) return;

    const float di = g_dinv[node];
    const float4* qr = (const float4*)(g_q1 + node * 16);
    float a[16];
#pragma unroll
    for (int c4 = 0; c4 < 4; c4++) {
        float4 v = qr[c4];
        a[c4*4+0] = fmaxf(fmaf(di, v.x, b1s[c4*4+0]), 0.f);
        a[c4*4+1] = fmaxf(fmaf(di, v.y, b1s[c4*4+1]), 0.f);
        a[c4*4+2] = fmaxf(fmaf(di, v.z, b1s[c4*4+2]), 0.f);
        a[c4*4+3] = fmaxf(fmaf(di, v.w, b1s[c4*4+3]), 0.f);
    }
    float o0 = 0.f, o1 = 0.f, o2 = 0.f;
#pragma unroll
    for (int ci = 0; ci < 16; ci++) {
        o0 = fmaf(a[ci], W2s[ci * 3 + 0], o0);
        o1 = fmaf(a[ci], W2s[ci * 3 + 1], o1);
        o2 = fmaf(a[ci], W2s[ci * 3 + 2], o2);
    }
    float4 r; r.x = o0 * di; r.y = o1 * di; r.z = o2 * di; r.w = 0.f;
    *(float4*)(g_p2 + node * 4) = r;
    *(float4*)(g_q2 + node * 4) = r;
}

// ============================================================================
// Edge aggregation layer 2: q2[dst] += p2[src]  (1 REDG.128/edge; w adds 0)
// ============================================================================
__global__ void edge_agg3_kernel(const int* __restrict__ ei)
{
    int e = blockIdx.x * 256 + threadIdx.x;
    if (e >= NE) return;
    int s = __ldg(ei + e), d = __ldg(ei + NE + e);
    float4 v = *(const float4*)(g_p2 + s * 4);
    red_add_v4(g_q2 + d * 4, v.x, v.y, v.z, v.w);
}

// ============================================================================
// Finalize: v = dinv*q2 + b2 ; log_softmax over 3 classes
// ============================================================================
__global__ void finalize_kernel(const float* __restrict__ b2g, float* __restrict__ out)
{
    int node = blockIdx.x * 256 + threadIdx.x;
    if (node >= NN) return;
    const float di = g_dinv[node];
    float4 q = *(const float4*)(g_q2 + node * 4);
    float v0 = fmaf(di, q.x, b2g[0]);
    float v1 = fmaf(di, q.y, b2g[1]);
    float v2 = fmaf(di, q.z, b2g[2]);
    float m = fmaxf(v0, fmaxf(v1, v2));
    float s = expf(v0 - m) + expf(v1 - m) + expf(v2 - m);
    float l = m + logf(s);
    out[node * 3 + 0] = v0 - l;
    out[node * 3 + 1] = v1 - l;
    out[node * 3 + 2] = v2 - l;
}

// ============================================================================
extern "C" void kernel_launch(void* const* d_in, const int* in_sizes, int n_in,
                              void* d_out, int out_size)
{
    const float* x   = (const float*)d_in[0];
    const float* c1w = (const float*)d_in[1];
    const float* c1b = (const float*)d_in[2];
    const float* c2w = (const float*)d_in[3];
    const float* c2b = (const float*)d_in[4];
    const float* g1w = (const float*)d_in[5];
    const float* g1b = (const float*)d_in[6];
    const float* g2w = (const float*)d_in[7];
    const float* g2b = (const float*)d_in[8];
    const int*   ei  = (const int*)d_in[9];
    float* out = (float*)d_out;

    const int nblk_node = (NN + 255) / 256;   // 118
    const int nblk_edge = (NE + 255) / 256;   // 3750

    deg_init_kernel <<<nblk_node, 256>>>();
    deg_count_kernel<<<nblk_edge, 256>>>(ei);
    dinv_kernel     <<<nblk_node, 256>>>();

    conv_fused_kernel<<<NN / 8, 256>>>(x, c1w, c1b, c2w, c2b);

    gcn1_pre_kernel <<<nblk_node, 256>>>(g1w);
    edge_agg16_kernel<<<(4 * NE + 255) / 256, 256>>>(ei);

    gcn2_pre_kernel <<<nblk_node, 256>>>(g1b, g2w);
    edge_agg3_kernel<<<nblk_edge, 256>>>(ei);

    finalize_kernel <<<nblk_node, 256>>>(g2b, out);
}